// round 4
// baseline (speedup 1.0000x reference)
#include <cuda_runtime.h>
#include <math.h>

// Problem constants
#define B_   64
#define S_   512
#define D_   1024
#define H_   1024
#define G_   4096      // 4*H
#define DPH  2048      // D + H
#define BS_  (B_ * S_) // 32768 rows of x

// ---------------------------------------------------------------------------
// Scratch (static device globals — no allocations allowed)
// ---------------------------------------------------------------------------
__device__ float g_Wt[(size_t)DPH * G_];        // W^T : [2048][4096]  (32 MB)
__device__ float g_Whp[(size_t)H_ * G_];        // packed Wh: [k][j][gate] (16 MB)
__device__ float g_Xg[(size_t)BS_ * G_];        // x @ Wx^T + b : [32768][4096] (512 MB)
__device__ float g_h[2][B_ * H_];               // double-buffered h state
__device__ float g_c[B_ * H_];                  // c state

// ---------------------------------------------------------------------------
// W [4096][2048] -> Wt [2048][4096]
// ---------------------------------------------------------------------------
__global__ void transpose_W(const float* __restrict__ W) {
    __shared__ float tile[32][33];
    int dk = blockIdx.x * 32 + threadIdx.x;   // 0..2047
    int n0 = blockIdx.y * 32;                 // 0..4095
#pragma unroll
    for (int i = 0; i < 32; i += 8)
        tile[threadIdx.y + i][threadIdx.x] = W[(size_t)(n0 + threadIdx.y + i) * DPH + dk];
    __syncthreads();
    int n2  = n0 + threadIdx.x;
    int dk2 = blockIdx.x * 32 + threadIdx.y;
#pragma unroll
    for (int i = 0; i < 32; i += 8)
        g_Wt[(size_t)(dk2 + i) * G_ + n2] = tile[threadIdx.x][threadIdx.y + i];
}

// ---------------------------------------------------------------------------
// Pack recurrent weights: Whp[(k*1024 + j)*4 + g] = Wt[1024 + k][g*1024 + j]
// so the 4 gate weights for (k, j) are contiguous (one float4).
// ---------------------------------------------------------------------------
__global__ void pack_Wh() {
    int idx = blockIdx.x * 256 + threadIdx.x;   // 0 .. 4M-1
    int g = idx & 3;
    int j = (idx >> 2) & 1023;
    int k = idx >> 12;
    g_Whp[idx] = g_Wt[(size_t)(1024 + k) * G_ + g * 1024 + j];
}

// ---------------------------------------------------------------------------
// Zero h (both buffers) and c
// ---------------------------------------------------------------------------
__global__ void zero_state() {
    int i = blockIdx.x * 256 + threadIdx.x;
    if (i < B_ * H_) {
        g_h[0][i] = 0.f;
        g_h[1][i] = 0.f;
        g_c[i]    = 0.f;
    }
}

// ---------------------------------------------------------------------------
// Input GEMM: Xg[m][n] = sum_k x[m][k] * Wt[k][n] + bias[n]
// M=32768, N=4096, K=1024.  128x128x16 tiles, 256 threads, 8x8 per thread,
// double-buffered shared memory.
// ---------------------------------------------------------------------------
__global__ __launch_bounds__(256) void sgemm_xw(const float* __restrict__ A,
                                                const float* __restrict__ bias) {
    const int K = D_, N = G_;
    __shared__ float As[2][16][128];   // transposed A tile
    __shared__ float Bs[2][16][128];

    int bn = blockIdx.x * 128;
    int bm = blockIdx.y * 128;
    int tid = threadIdx.x;
    int tx = tid & 15, ty = tid >> 4;

    // global-load indexing
    int a_r0 = tid >> 2;            // 0..63
    int a_k0 = (tid & 3) * 4;       // {0,4,8,12}
    int b_k0 = tid >> 5;            // 0..7
    int b_n0 = (tid & 31) * 4;      // 0..124

    float4 ra0, ra1, rb0, rb1;
    float acc[8][8];
#pragma unroll
    for (int i = 0; i < 8; i++)
#pragma unroll
        for (int j = 0; j < 8; j++) acc[i][j] = 0.f;

    const int NC = K / 16;

    // prologue: chunk 0
    {
        int k0 = 0;
        ra0 = *(const float4*)&A[(size_t)(bm + a_r0) * K + k0 + a_k0];
        ra1 = *(const float4*)&A[(size_t)(bm + a_r0 + 64) * K + k0 + a_k0];
        rb0 = *(const float4*)&g_Wt[(size_t)(k0 + b_k0) * N + bn + b_n0];
        rb1 = *(const float4*)&g_Wt[(size_t)(k0 + b_k0 + 8) * N + bn + b_n0];
        As[0][a_k0 + 0][a_r0] = ra0.x; As[0][a_k0 + 1][a_r0] = ra0.y;
        As[0][a_k0 + 2][a_r0] = ra0.z; As[0][a_k0 + 3][a_r0] = ra0.w;
        As[0][a_k0 + 0][a_r0 + 64] = ra1.x; As[0][a_k0 + 1][a_r0 + 64] = ra1.y;
        As[0][a_k0 + 2][a_r0 + 64] = ra1.z; As[0][a_k0 + 3][a_r0 + 64] = ra1.w;
        *(float4*)&Bs[0][b_k0][b_n0]     = rb0;
        *(float4*)&Bs[0][b_k0 + 8][b_n0] = rb1;
    }
    __syncthreads();

    for (int kc = 0; kc < NC; ++kc) {
        int buf = kc & 1;
        if (kc + 1 < NC) {
            int k0 = (kc + 1) * 16;
            ra0 = *(const float4*)&A[(size_t)(bm + a_r0) * K + k0 + a_k0];
            ra1 = *(const float4*)&A[(size_t)(bm + a_r0 + 64) * K + k0 + a_k0];
            rb0 = *(const float4*)&g_Wt[(size_t)(k0 + b_k0) * N + bn + b_n0];
            rb1 = *(const float4*)&g_Wt[(size_t)(k0 + b_k0 + 8) * N + bn + b_n0];
        }
#pragma unroll
        for (int k = 0; k < 16; k++) {
            float af[8], bf[8];
            *(float4*)&af[0] = *(const float4*)&As[buf][k][ty * 8];
            *(float4*)&af[4] = *(const float4*)&As[buf][k][ty * 8 + 4];
            *(float4*)&bf[0] = *(const float4*)&Bs[buf][k][tx * 8];
            *(float4*)&bf[4] = *(const float4*)&Bs[buf][k][tx * 8 + 4];
#pragma unroll
            for (int i = 0; i < 8; i++)
#pragma unroll
                for (int j = 0; j < 8; j++)
                    acc[i][j] += af[i] * bf[j];
        }
        if (kc + 1 < NC) {
            int nb = buf ^ 1;
            As[nb][a_k0 + 0][a_r0] = ra0.x; As[nb][a_k0 + 1][a_r0] = ra0.y;
            As[nb][a_k0 + 2][a_r0] = ra0.z; As[nb][a_k0 + 3][a_r0] = ra0.w;
            As[nb][a_k0 + 0][a_r0 + 64] = ra1.x; As[nb][a_k0 + 1][a_r0 + 64] = ra1.y;
            As[nb][a_k0 + 2][a_r0 + 64] = ra1.z; As[nb][a_k0 + 3][a_r0 + 64] = ra1.w;
            *(float4*)&Bs[nb][b_k0][b_n0]     = rb0;
            *(float4*)&Bs[nb][b_k0 + 8][b_n0] = rb1;
        }
        __syncthreads();
    }

    // epilogue with bias
#pragma unroll
    for (int i = 0; i < 8; i++) {
        size_t m = (size_t)(bm + ty * 8 + i);
#pragma unroll
        for (int j = 0; j < 8; j += 4) {
            int n = bn + tx * 8 + j;
            float4 v;
            v.x = acc[i][j + 0] + bias[n + 0];
            v.y = acc[i][j + 1] + bias[n + 1];
            v.z = acc[i][j + 2] + bias[n + 2];
            v.w = acc[i][j + 3] + bias[n + 3];
            *(float4*)&g_Xg[m * N + n] = v;
        }
    }
}

// ---------------------------------------------------------------------------
// One LSTM timestep.
// Grid: 128 blocks, each owns 8 j-columns (all 4 gates for them) across all
// 64 batches. Thread tile: 2 batches x 1 j x 4 gates = 8 accumulators.
// gates = h_in @ Wh^T (+Xg already holds x-part + bias), then update c/h.
// ---------------------------------------------------------------------------
__global__ __launch_bounds__(256) void lstm_step(float* __restrict__ out, int t) {
    __shared__ float hs[64][65];                    // [b][k within chunk]
    __shared__ __align__(16) float ws[64][36];      // [k][jj*4 + gate]

    const float* __restrict__ h_in = g_h[t & 1];
    float* __restrict__ h_out = g_h[(t + 1) & 1];

    int tid  = threadIdx.x;
    int lane = tid & 31, w = tid >> 5;
    int jj = tid & 7, bp = tid >> 3;                // bp: 0..31
    int b0 = bp * 2, b1 = b0 + 1;
    int j0 = blockIdx.x * 8;
    int j  = j0 + jj;

    float4 acc0 = {0.f, 0.f, 0.f, 0.f};
    float4 acc1 = {0.f, 0.f, 0.f, 0.f};

    for (int kc = 0; kc < 16; ++kc) {
        int k0 = kc * 64;
        // stage h tile: each warp loads one b-row per pass (coalesced)
#pragma unroll
        for (int p = 0; p < 8; ++p) {
            int b = p * 8 + w;
            hs[b][lane]      = h_in[b * H_ + k0 + lane];
            hs[b][32 + lane] = h_in[b * H_ + k0 + 32 + lane];
        }
        // stage packed weights: contiguous 128B rows
#pragma unroll
        for (int i = 0; i < 8; ++i) {
            int e = tid + i * 256;
            int k = e >> 5, cc = e & 31;
            ws[k][cc] = g_Whp[(size_t)(k0 + k) * G_ + j0 * 4 + cc];
        }
        __syncthreads();
#pragma unroll 16
        for (int k = 0; k < 64; ++k) {
            float4 wv = *(const float4*)&ws[k][jj * 4];
            float h0 = hs[b0][k];
            float h1 = hs[b1][k];
            acc0.x += h0 * wv.x; acc0.y += h0 * wv.y;
            acc0.z += h0 * wv.z; acc0.w += h0 * wv.w;
            acc1.x += h1 * wv.x; acc1.y += h1 * wv.y;
            acc1.z += h1 * wv.z; acc1.w += h1 * wv.w;
        }
        __syncthreads();
    }

    // gate math + state update (this block exclusively owns (b, j))
#pragma unroll
    for (int s = 0; s < 2; ++s) {
        int b = (s == 0) ? b0 : b1;
        float4 a = (s == 0) ? acc0 : acc1;
        size_t m = (size_t)b * S_ + t;
        const float* xg = &g_Xg[m * G_];
        float gi = a.x + xg[j];
        float gf = a.y + xg[1024 + j];
        float go = a.z + xg[2048 + j];
        float gg = a.w + xg[3072 + j];
        float ii = 1.f / (1.f + expf(-gi));
        float ff = 1.f / (1.f + expf(-gf));
        float oo = 1.f / (1.f + expf(-go));
        float cn = ff * g_c[b * H_ + j] + ii * tanhf(gg);
        float hn = oo * tanhf(cn);
        g_c[b * H_ + j]   = cn;
        h_out[b * H_ + j] = hn;
        out[((size_t)b * S_ + t) * H_ + j] = hn;
    }
}

// ---------------------------------------------------------------------------
// Final (h, c) tail, guarded by out_size (outputs, h, c flattening order)
// ---------------------------------------------------------------------------
__global__ void write_tail(float* __restrict__ out, long long out_size) {
    int i = blockIdx.x * 256 + threadIdx.x;
    if (i >= B_ * H_) return;
    long long base = (long long)B_ * S_ * H_;
    if (base + i < out_size)               out[base + i]               = g_h[0][i]; // 512 steps -> buffer 0
    if (base + B_ * H_ + i < out_size)     out[base + B_ * H_ + i]     = g_c[i];
}

// ---------------------------------------------------------------------------
extern "C" void kernel_launch(void* const* d_in, const int* in_sizes, int n_in,
                              void* d_out, int out_size) {
    const float* x    = (const float*)d_in[0];   // [64, 512, 1024]
    const float* W    = (const float*)d_in[1];   // [4096, 2048]
    const float* bias = (const float*)d_in[2];   // [4096]
    float* out = (float*)d_out;

    transpose_W<<<dim3(64, 128), dim3(32, 8)>>>(W);
    pack_Wh<<<(H_ * G_) / 256, 256>>>();
    zero_state<<<(B_ * H_ + 255) / 256, 256>>>();
    sgemm_xw<<<dim3(G_ / 128, BS_ / 128), 256>>>(x, bias);

    for (int t = 0; t < S_; ++t)
        lstm_step<<<128, 256>>>(out, t);

    write_tail<<<(B_ * H_ + 255) / 256, 256>>>(out, (long long)out_size);
}

// round 5
// speedup vs baseline: 1.3411x; 1.3411x over previous
#include <cuda_runtime.h>
#include <math.h>

// Problem constants
#define B_   64
#define S_   512
#define D_   1024
#define H_   1024
#define G_   4096      // 4*H
#define DPH  2048      // D + H
#define BS_  (B_ * S_) // 32768 rows of x

typedef unsigned long long ull;

// ---------------------------------------------------------------------------
// Packed fp32x2 helpers (Blackwell FFMA2 — full-rate fp32 path)
// ---------------------------------------------------------------------------
__device__ __forceinline__ ull ffma2(ull a, ull b, ull c) {
    ull d;
    asm("fma.rn.f32x2 %0, %1, %2, %3;" : "=l"(d) : "l"(a), "l"(b), "l"(c));
    return d;
}
__device__ __forceinline__ ull dup2(float x) {
    ull d; unsigned xi = __float_as_uint(x);
    asm("mov.b64 %0, {%1, %1};" : "=l"(d) : "r"(xi));
    return d;
}
__device__ __forceinline__ float lo2(ull v) { return __uint_as_float((unsigned)v); }
__device__ __forceinline__ float hi2(ull v) { return __uint_as_float((unsigned)(v >> 32)); }

__device__ __forceinline__ void cp16(void* smem, const void* g) {
    unsigned s = (unsigned)__cvta_generic_to_shared(smem);
    asm volatile("cp.async.cg.shared.global [%0], [%1], 16;" :: "r"(s), "l"(g));
}

// ---------------------------------------------------------------------------
// Scratch (static device globals — no allocations allowed)
// ---------------------------------------------------------------------------
__device__ float g_Wt[(size_t)DPH * G_];        // W^T : [2048][4096]  (32 MB)
__device__ float g_Whp[(size_t)H_ * G_];        // packed Wh: [k][j][gate] (16 MB)
__device__ float g_Xg[(size_t)BS_ * G_];        // x @ Wx^T + b : [32768][4096] (512 MB)
__device__ float2 g_hd[2][H_][B_];              // h state, k-major, duplicated (h,h)
__device__ float g_c[B_ * H_];                  // c state [b][j]

// ---------------------------------------------------------------------------
// W [4096][2048] -> Wt [2048][4096]
// ---------------------------------------------------------------------------
__global__ void transpose_W(const float* __restrict__ W) {
    __shared__ float tile[32][33];
    int dk = blockIdx.x * 32 + threadIdx.x;   // 0..2047
    int n0 = blockIdx.y * 32;                 // 0..4095
#pragma unroll
    for (int i = 0; i < 32; i += 8)
        tile[threadIdx.y + i][threadIdx.x] = W[(size_t)(n0 + threadIdx.y + i) * DPH + dk];
    __syncthreads();
    int n2  = n0 + threadIdx.x;
    int dk2 = blockIdx.x * 32 + threadIdx.y;
#pragma unroll
    for (int i = 0; i < 32; i += 8)
        g_Wt[(size_t)(dk2 + i) * G_ + n2] = tile[threadIdx.x][threadIdx.y + i];
}

// ---------------------------------------------------------------------------
// Pack recurrent weights: Whp[(k*1024 + j)*4 + g] = Wt[1024 + k][g*1024 + j]
// gates (i,f,o,g) contiguous per (k, j) -> natural (i,f) / (o,g) f32x2 pairs.
// ---------------------------------------------------------------------------
__global__ void pack_Wh() {
    int idx = blockIdx.x * 256 + threadIdx.x;   // 0 .. 4M-1
    int g = idx & 3;
    int j = (idx >> 2) & 1023;
    int k = idx >> 12;
    g_Whp[idx] = g_Wt[(size_t)(1024 + k) * G_ + g * 1024 + j];
}

// ---------------------------------------------------------------------------
// Zero h (buffer 0, duplicated layout) and c
// ---------------------------------------------------------------------------
__global__ void zero_state() {
    int i = blockIdx.x * 256 + threadIdx.x;
    if (i < B_ * H_) {
        int j = i >> 6, b = i & 63;
        g_hd[0][j][b] = make_float2(0.f, 0.f);
        g_c[i] = 0.f;
    }
}

// ---------------------------------------------------------------------------
// Input GEMM: Xg[m][n] = sum_k x[m][k] * Wt[k][n] + bias[n]
// M=32768, N=4096, K=1024.  128x128x16 tiles, 256 threads, 8x8 per thread,
// double-buffered shared memory, FFMA2 inner product.
// ---------------------------------------------------------------------------
__global__ __launch_bounds__(256) void sgemm_xw(const float* __restrict__ A,
                                                const float* __restrict__ bias) {
    const int K = D_, N = G_;
    __shared__ __align__(16) float As[2][16][128];   // transposed A tile
    __shared__ __align__(16) float Bs[2][16][128];

    int bn = blockIdx.x * 128;
    int bm = blockIdx.y * 128;
    int tid = threadIdx.x;
    int tx = tid & 15, ty = tid >> 4;

    // global-load indexing
    int a_r0 = tid >> 2;            // 0..63
    int a_k0 = (tid & 3) * 4;       // {0,4,8,12}
    int b_k0 = tid >> 5;            // 0..7
    int b_n0 = (tid & 31) * 4;      // 0..124

    float4 ra0, ra1, rb0, rb1;
    ull acc2[8][4];
#pragma unroll
    for (int i = 0; i < 8; i++)
#pragma unroll
        for (int j = 0; j < 4; j++) acc2[i][j] = 0ull;

    const int NC = K / 16;

    // prologue: chunk 0
    {
        int k0 = 0;
        ra0 = *(const float4*)&A[(size_t)(bm + a_r0) * K + k0 + a_k0];
        ra1 = *(const float4*)&A[(size_t)(bm + a_r0 + 64) * K + k0 + a_k0];
        rb0 = *(const float4*)&g_Wt[(size_t)(k0 + b_k0) * N + bn + b_n0];
        rb1 = *(const float4*)&g_Wt[(size_t)(k0 + b_k0 + 8) * N + bn + b_n0];
        As[0][a_k0 + 0][a_r0] = ra0.x; As[0][a_k0 + 1][a_r0] = ra0.y;
        As[0][a_k0 + 2][a_r0] = ra0.z; As[0][a_k0 + 3][a_r0] = ra0.w;
        As[0][a_k0 + 0][a_r0 + 64] = ra1.x; As[0][a_k0 + 1][a_r0 + 64] = ra1.y;
        As[0][a_k0 + 2][a_r0 + 64] = ra1.z; As[0][a_k0 + 3][a_r0 + 64] = ra1.w;
        *(float4*)&Bs[0][b_k0][b_n0]     = rb0;
        *(float4*)&Bs[0][b_k0 + 8][b_n0] = rb1;
    }
    __syncthreads();

    for (int kc = 0; kc < NC; ++kc) {
        int buf = kc & 1;
        if (kc + 1 < NC) {
            int k0 = (kc + 1) * 16;
            ra0 = *(const float4*)&A[(size_t)(bm + a_r0) * K + k0 + a_k0];
            ra1 = *(const float4*)&A[(size_t)(bm + a_r0 + 64) * K + k0 + a_k0];
            rb0 = *(const float4*)&g_Wt[(size_t)(k0 + b_k0) * N + bn + b_n0];
            rb1 = *(const float4*)&g_Wt[(size_t)(k0 + b_k0 + 8) * N + bn + b_n0];
        }
#pragma unroll
        for (int k = 0; k < 16; k++) {
            float af[8];
            *(float4*)&af[0] = *(const float4*)&As[buf][k][ty * 8];
            *(float4*)&af[4] = *(const float4*)&As[buf][k][ty * 8 + 4];
            ulonglong2 bA = *(const ulonglong2*)&Bs[buf][k][tx * 8];
            ulonglong2 bB = *(const ulonglong2*)&Bs[buf][k][tx * 8 + 4];
#pragma unroll
            for (int i = 0; i < 8; i++) {
                ull ad = dup2(af[i]);
                acc2[i][0] = ffma2(ad, bA.x, acc2[i][0]);
                acc2[i][1] = ffma2(ad, bA.y, acc2[i][1]);
                acc2[i][2] = ffma2(ad, bB.x, acc2[i][2]);
                acc2[i][3] = ffma2(ad, bB.y, acc2[i][3]);
            }
        }
        if (kc + 1 < NC) {
            int nb = buf ^ 1;
            As[nb][a_k0 + 0][a_r0] = ra0.x; As[nb][a_k0 + 1][a_r0] = ra0.y;
            As[nb][a_k0 + 2][a_r0] = ra0.z; As[nb][a_k0 + 3][a_r0] = ra0.w;
            As[nb][a_k0 + 0][a_r0 + 64] = ra1.x; As[nb][a_k0 + 1][a_r0 + 64] = ra1.y;
            As[nb][a_k0 + 2][a_r0 + 64] = ra1.z; As[nb][a_k0 + 3][a_r0 + 64] = ra1.w;
            *(float4*)&Bs[nb][b_k0][b_n0]     = rb0;
            *(float4*)&Bs[nb][b_k0 + 8][b_n0] = rb1;
        }
        __syncthreads();
    }

    // epilogue with bias (unpack f32x2 pairs: pair jp -> cols 2jp, 2jp+1)
#pragma unroll
    for (int i = 0; i < 8; i++) {
        size_t m = (size_t)(bm + ty * 8 + i);
        int n = bn + tx * 8;
        float4 v0, v1;
        v0.x = lo2(acc2[i][0]) + bias[n + 0];
        v0.y = hi2(acc2[i][0]) + bias[n + 1];
        v0.z = lo2(acc2[i][1]) + bias[n + 2];
        v0.w = hi2(acc2[i][1]) + bias[n + 3];
        v1.x = lo2(acc2[i][2]) + bias[n + 4];
        v1.y = hi2(acc2[i][2]) + bias[n + 5];
        v1.z = lo2(acc2[i][3]) + bias[n + 6];
        v1.w = hi2(acc2[i][3]) + bias[n + 7];
        *(float4*)&g_Xg[m * N + n]     = v0;
        *(float4*)&g_Xg[m * N + n + 4] = v1;
    }
}

// ---------------------------------------------------------------------------
// One LSTM timestep (FFMA2 + cp.async double-buffered staging).
// Grid: 128 blocks; block owns 8 j-columns (all 4 gates) x all 64 batches.
// Thread: jj (0..7) x bp (0..31) -> 2 batches, gate pairs (i,f) and (o,g).
// h state lives in g_hd[buf][k][b] pre-duplicated (h,h) -> staging is a
// straight contiguous bulk copy, no transpose, no duplication work.
// ---------------------------------------------------------------------------
__global__ __launch_bounds__(256) void lstm_step(float* __restrict__ out, int t) {
    __shared__ __align__(16) float2 hbuf[2][32][64];   // 32 KB
    __shared__ __align__(16) float  wbuf[2][32][32];   //  8 KB

    const int tid = threadIdx.x;
    const int jj = tid & 7, bp = tid >> 3;
    const int b0 = bp * 2, b1 = b0 + 1;
    const int j0 = blockIdx.x * 8;
    const int j  = j0 + jj;
    const int inb  = t & 1;
    const int outb = (t + 1) & 1;

    const float2* __restrict__ hin = &g_hd[inb][0][0];

    // stage one 32-k chunk (h: 16KB contiguous; w: 32 rows x 128B)
    auto stage = [&](int kc, int buf) {
        int k0 = kc * 32;
        const char* hsrc = (const char*)(hin + (size_t)k0 * 64);
        char* hdst = (char*)&hbuf[buf][0][0];
#pragma unroll
        for (int i = 0; i < 4; ++i) {
            int off = (tid + i * 256) * 16;
            cp16(hdst + off, hsrc + off);
        }
        int k = tid >> 3, seg = tid & 7;
        cp16(&wbuf[buf][k][seg * 4],
             &g_Whp[(size_t)(k0 + k) * G_ + j0 * 4 + seg * 4]);
    };

    ull a0if = 0ull, a0og = 0ull, a1if = 0ull, a1og = 0ull;

    stage(0, 0);
    asm volatile("cp.async.commit_group;" ::: "memory");

    for (int kc = 0; kc < 32; ++kc) {
        int buf = kc & 1;
        if (kc + 1 < 32) {
            stage(kc + 1, buf ^ 1);
            asm volatile("cp.async.commit_group;" ::: "memory");
            asm volatile("cp.async.wait_group 1;" ::: "memory");
        } else {
            asm volatile("cp.async.wait_group 0;" ::: "memory");
        }
        __syncthreads();
#pragma unroll
        for (int k = 0; k < 32; ++k) {
            ulonglong2 wp = *(const ulonglong2*)&wbuf[buf][k][jj * 4];
            ull h0 = *(const ull*)&hbuf[buf][k][b0];
            ull h1 = *(const ull*)&hbuf[buf][k][b1];
            a0if = ffma2(h0, wp.x, a0if);
            a0og = ffma2(h0, wp.y, a0og);
            a1if = ffma2(h1, wp.x, a1if);
            a1og = ffma2(h1, wp.y, a1og);
        }
        __syncthreads();
    }

    // gate math + state update (this block exclusively owns (b, j))
    float res[2][4] = {
        { lo2(a0if), hi2(a0if), lo2(a0og), hi2(a0og) },
        { lo2(a1if), hi2(a1if), lo2(a1og), hi2(a1og) }
    };
#pragma unroll
    for (int s = 0; s < 2; ++s) {
        int b = s ? b1 : b0;
        const float* xg = &g_Xg[((size_t)b * S_ + t) * G_];
        float gi = res[s][0] + xg[j];
        float gf = res[s][1] + xg[1024 + j];
        float go = res[s][2] + xg[2048 + j];
        float gg = res[s][3] + xg[3072 + j];
        float ii = 1.f / (1.f + expf(-gi));
        float ff = 1.f / (1.f + expf(-gf));
        float oo = 1.f / (1.f + expf(-go));
        float cn = ff * g_c[b * H_ + j] + ii * tanhf(gg);
        float hn = oo * tanhf(cn);
        g_c[b * H_ + j]   = cn;
        g_hd[outb][j][b]  = make_float2(hn, hn);
        out[((size_t)b * S_ + t) * H_ + j] = hn;
    }
}

// ---------------------------------------------------------------------------
// Final (h, c) tail, guarded by out_size (outputs, h, c flattening order)
// ---------------------------------------------------------------------------
__global__ void write_tail(float* __restrict__ out, long long out_size) {
    int i = blockIdx.x * 256 + threadIdx.x;
    if (i >= B_ * H_) return;
    long long base = (long long)B_ * S_ * H_;
    int b = i >> 10, j = i & 1023;
    // after t = 511, h_out buffer = (511+1)&1 = 0
    if (base + i < out_size)           out[base + i]           = g_hd[0][j][b].x;
    if (base + B_ * H_ + i < out_size) out[base + B_ * H_ + i] = g_c[i];
}

// ---------------------------------------------------------------------------
extern "C" void kernel_launch(void* const* d_in, const int* in_sizes, int n_in,
                              void* d_out, int out_size) {
    const float* x    = (const float*)d_in[0];   // [64, 512, 1024]
    const float* W    = (const float*)d_in[1];   // [4096, 2048]
    const float* bias = (const float*)d_in[2];   // [4096]
    float* out = (float*)d_out;

    transpose_W<<<dim3(64, 128), dim3(32, 8)>>>(W);
    pack_Wh<<<(H_ * G_) / 256, 256>>>();
    zero_state<<<(B_ * H_ + 255) / 256, 256>>>();
    sgemm_xw<<<dim3(G_ / 128, BS_ / 128), 256>>>(x, bias);

    for (int t = 0; t < S_; ++t)
        lstm_step<<<128, 256>>>(out, t);

    write_tail<<<(B_ * H_ + 255) / 256, 256>>>(out, (long long)out_size);
}

// round 7
// speedup vs baseline: 1.5990x; 1.1923x over previous
#include <cuda_runtime.h>
#include <math.h>

// Problem constants
#define B_   64
#define S_   512
#define D_   1024
#define H_   1024
#define G_   4096      // 4*H
#define DPH  2048      // D + H
#define BS_  (B_ * S_) // 32768 rows of x
#define NBLK 128       // persistent grid (<=148 SMs, 1 block/SM)

typedef unsigned long long ull;

// ---------------------------------------------------------------------------
// Packed fp32x2 helpers (Blackwell FFMA2 — full-rate fp32 path)
// ---------------------------------------------------------------------------
__device__ __forceinline__ ull ffma2(ull a, ull b, ull c) {
    ull d;
    asm("fma.rn.f32x2 %0, %1, %2, %3;" : "=l"(d) : "l"(a), "l"(b), "l"(c));
    return d;
}
__device__ __forceinline__ ull dup2(float x) {
    ull d; unsigned xi = __float_as_uint(x);
    asm("mov.b64 %0, {%1, %1};" : "=l"(d) : "r"(xi));
    return d;
}
__device__ __forceinline__ float lo2(ull v) { return __uint_as_float((unsigned)v); }
__device__ __forceinline__ float hi2(ull v) { return __uint_as_float((unsigned)(v >> 32)); }

__device__ __forceinline__ void cp16(void* smem, const void* g) {
    unsigned s = (unsigned)__cvta_generic_to_shared(smem);
    asm volatile("cp.async.cg.shared.global [%0], [%1], 16;" :: "r"(s), "l"(g));
}

// ---------------------------------------------------------------------------
// Scratch (static device globals — no allocations allowed)
// ---------------------------------------------------------------------------
__device__ float g_Wt[(size_t)DPH * G_];          // W^T : [2048][4096]  (32 MB)
__device__ float g_Whp[(size_t)H_ * G_];          // packed Wh: [k][j][gate] (16 MB)
__device__ float g_Xg[(size_t)BS_ * G_];          // x @ Wx^T + b (512 MB)
__device__ __align__(16) float g_h[2][H_][B_];    // h state, k-major, NOT duplicated
__device__ volatile unsigned g_bar_gen;
__device__ unsigned g_bar_count;

// ---------------------------------------------------------------------------
// W [4096][2048] -> Wt [2048][4096]
// ---------------------------------------------------------------------------
__global__ void transpose_W(const float* __restrict__ W) {
    __shared__ float tile[32][33];
    int dk = blockIdx.x * 32 + threadIdx.x;
    int n0 = blockIdx.y * 32;
#pragma unroll
    for (int i = 0; i < 32; i += 8)
        tile[threadIdx.y + i][threadIdx.x] = W[(size_t)(n0 + threadIdx.y + i) * DPH + dk];
    __syncthreads();
    int n2  = n0 + threadIdx.x;
    int dk2 = blockIdx.x * 32 + threadIdx.y;
#pragma unroll
    for (int i = 0; i < 32; i += 8)
        g_Wt[(size_t)(dk2 + i) * G_ + n2] = tile[threadIdx.x][threadIdx.y + i];
}

// ---------------------------------------------------------------------------
// Pack recurrent weights: Whp[(k*1024 + j)*4 + g] = Wt[1024 + k][g*1024 + j]
// gates (i,f,o,g) contiguous per (k, j) -> natural (i,f) / (o,g) f32x2 pairs.
// ---------------------------------------------------------------------------
__global__ void pack_Wh() {
    int idx = blockIdx.x * 256 + threadIdx.x;
    int g = idx & 3;
    int j = (idx >> 2) & 1023;
    int k = idx >> 12;
    g_Whp[idx] = g_Wt[(size_t)(1024 + k) * G_ + g * 1024 + j];
}

// ---------------------------------------------------------------------------
// Zero h buffers, reset grid barrier
// ---------------------------------------------------------------------------
__global__ void zero_state() {
    int i = blockIdx.x * 256 + threadIdx.x;
    if (i < B_ * H_) {
        int j = i >> 6, b = i & 63;
        g_h[0][j][b] = 0.f;
        g_h[1][j][b] = 0.f;
    }
    if (i == 0) { g_bar_count = 0; g_bar_gen = 0; }
}

// ---------------------------------------------------------------------------
// Input GEMM: Xg[m][n] = sum_k x[m][k] * Wt[k][n] + bias[n]
// M=32768, N=4096, K=1024. 128x128x16 tiles, 256 threads, 8x8/thread, FFMA2.
// ---------------------------------------------------------------------------
__global__ __launch_bounds__(256) void sgemm_xw(const float* __restrict__ A,
                                                const float* __restrict__ bias) {
    const int K = D_, N = G_;
    __shared__ __align__(16) float As[2][16][128];
    __shared__ __align__(16) float Bs[2][16][128];

    int bn = blockIdx.x * 128;
    int bm = blockIdx.y * 128;
    int tid = threadIdx.x;
    int tx = tid & 15, ty = tid >> 4;

    int a_r0 = tid >> 2;
    int a_k0 = (tid & 3) * 4;
    int b_k0 = tid >> 5;
    int b_n0 = (tid & 31) * 4;

    float4 ra0, ra1, rb0, rb1;
    ull acc2[8][4];
#pragma unroll
    for (int i = 0; i < 8; i++)
#pragma unroll
        for (int j = 0; j < 4; j++) acc2[i][j] = 0ull;

    const int NC = K / 16;

    {
        int k0 = 0;
        ra0 = *(const float4*)&A[(size_t)(bm + a_r0) * K + k0 + a_k0];
        ra1 = *(const float4*)&A[(size_t)(bm + a_r0 + 64) * K + k0 + a_k0];
        rb0 = *(const float4*)&g_Wt[(size_t)(k0 + b_k0) * N + bn + b_n0];
        rb1 = *(const float4*)&g_Wt[(size_t)(k0 + b_k0 + 8) * N + bn + b_n0];
        As[0][a_k0 + 0][a_r0] = ra0.x; As[0][a_k0 + 1][a_r0] = ra0.y;
        As[0][a_k0 + 2][a_r0] = ra0.z; As[0][a_k0 + 3][a_r0] = ra0.w;
        As[0][a_k0 + 0][a_r0 + 64] = ra1.x; As[0][a_k0 + 1][a_r0 + 64] = ra1.y;
        As[0][a_k0 + 2][a_r0 + 64] = ra1.z; As[0][a_k0 + 3][a_r0 + 64] = ra1.w;
        *(float4*)&Bs[0][b_k0][b_n0]     = rb0;
        *(float4*)&Bs[0][b_k0 + 8][b_n0] = rb1;
    }
    __syncthreads();

    for (int kc = 0; kc < NC; ++kc) {
        int buf = kc & 1;
        if (kc + 1 < NC) {
            int k0 = (kc + 1) * 16;
            ra0 = *(const float4*)&A[(size_t)(bm + a_r0) * K + k0 + a_k0];
            ra1 = *(const float4*)&A[(size_t)(bm + a_r0 + 64) * K + k0 + a_k0];
            rb0 = *(const float4*)&g_Wt[(size_t)(k0 + b_k0) * N + bn + b_n0];
            rb1 = *(const float4*)&g_Wt[(size_t)(k0 + b_k0 + 8) * N + bn + b_n0];
        }
#pragma unroll
        for (int k = 0; k < 16; k++) {
            float af[8];
            *(float4*)&af[0] = *(const float4*)&As[buf][k][ty * 8];
            *(float4*)&af[4] = *(const float4*)&As[buf][k][ty * 8 + 4];
            ulonglong2 bA = *(const ulonglong2*)&Bs[buf][k][tx * 8];
            ulonglong2 bB = *(const ulonglong2*)&Bs[buf][k][tx * 8 + 4];
#pragma unroll
            for (int i = 0; i < 8; i++) {
                ull ad = dup2(af[i]);
                acc2[i][0] = ffma2(ad, bA.x, acc2[i][0]);
                acc2[i][1] = ffma2(ad, bA.y, acc2[i][1]);
                acc2[i][2] = ffma2(ad, bB.x, acc2[i][2]);
                acc2[i][3] = ffma2(ad, bB.y, acc2[i][3]);
            }
        }
        if (kc + 1 < NC) {
            int nb = buf ^ 1;
            As[nb][a_k0 + 0][a_r0] = ra0.x; As[nb][a_k0 + 1][a_r0] = ra0.y;
            As[nb][a_k0 + 2][a_r0] = ra0.z; As[nb][a_k0 + 3][a_r0] = ra0.w;
            As[nb][a_k0 + 0][a_r0 + 64] = ra1.x; As[nb][a_k0 + 1][a_r0 + 64] = ra1.y;
            As[nb][a_k0 + 2][a_r0 + 64] = ra1.z; As[nb][a_k0 + 3][a_r0 + 64] = ra1.w;
            *(float4*)&Bs[nb][b_k0][b_n0]     = rb0;
            *(float4*)&Bs[nb][b_k0 + 8][b_n0] = rb1;
        }
        __syncthreads();
    }

#pragma unroll
    for (int i = 0; i < 8; i++) {
        size_t m = (size_t)(bm + ty * 8 + i);
        int n = bn + tx * 8;
        float4 v0, v1;
        v0.x = lo2(acc2[i][0]) + bias[n + 0];
        v0.y = hi2(acc2[i][0]) + bias[n + 1];
        v0.z = lo2(acc2[i][1]) + bias[n + 2];
        v0.w = hi2(acc2[i][1]) + bias[n + 3];
        v1.x = lo2(acc2[i][2]) + bias[n + 4];
        v1.y = hi2(acc2[i][2]) + bias[n + 5];
        v1.z = lo2(acc2[i][3]) + bias[n + 6];
        v1.w = hi2(acc2[i][3]) + bias[n + 7];
        *(float4*)&g_Xg[m * N + n]     = v0;
        *(float4*)&g_Xg[m * N + n + 4] = v1;
    }
}

// ---------------------------------------------------------------------------
// Device-wide barrier (all NBLK blocks resident by construction).
// ---------------------------------------------------------------------------
__device__ __forceinline__ void grid_barrier() {
    __syncthreads();
    if (threadIdx.x == 0) {
        __threadfence();
        unsigned gen = g_bar_gen;
        if (atomicAdd(&g_bar_count, 1u) == NBLK - 1) {
            g_bar_count = 0;
            __threadfence();
            g_bar_gen = gen + 1;
        } else {
            while (g_bar_gen == gen) { }
        }
        __threadfence();
    }
    __syncthreads();
}

// ---------------------------------------------------------------------------
// Persistent LSTM: all 512 timesteps in one kernel.
// 128 blocks; block owns 8 j-columns (all 4 gates) x all 64 batches.
// Weight slice (128 KB) resident in smem for the whole kernel.
// h staged per 64-k chunk via double-buffered cp.async (16 KB/chunk).
// c state lives in registers across all steps.
// Dynamic smem: ws[1024][32] (128 KB) + hb[2][64][64] (32 KB) = 160 KB.
// ---------------------------------------------------------------------------
__global__ __launch_bounds__(256) void lstm_persistent(float* __restrict__ out,
                                                       long long out_size) {
    extern __shared__ __align__(16) float sm[];
    float* ws = sm;               // [k][32]  : 32768 floats
    float* hb = sm + 32768;       // [2][64][64] : 8192 floats

    const int tid = threadIdx.x;
    const int jj = tid & 7, bp = tid >> 3;
    const int b0 = bp * 2, b1 = b0 + 1;
    const int j0 = blockIdx.x * 8;
    const int j  = j0 + jj;

    // preload this block's weight slice once (1024 rows x 128 B)
    for (int i = tid; i < 8192; i += 256) {
        int r = i >> 3, seg = (i & 7) * 4;
        cp16(&ws[r * 32 + seg], &g_Whp[(size_t)r * G_ + j0 * 4 + seg]);
    }
    asm volatile("cp.async.commit_group;" ::: "memory");
    asm volatile("cp.async.wait_group 0;" ::: "memory");
    __syncthreads();

    float c0 = 0.f, c1 = 0.f, hn0 = 0.f, hn1 = 0.f;

    for (int t = 0; t < S_; ++t) {
        const float* __restrict__ hin  = &g_h[t & 1][0][0];
        float* __restrict__       hout = &g_h[(t + 1) & 1][0][0];

        // prefetch x-gate biases for this step (consumed ~10us later)
        const float* xg0 = &g_Xg[((size_t)b0 * S_ + t) * G_];
        const float* xg1 = &g_Xg[((size_t)b1 * S_ + t) * G_];
        float xi0 = xg0[j], xf0 = xg0[1024 + j], xo0 = xg0[2048 + j], xq0 = xg0[3072 + j];
        float xi1 = xg1[j], xf1 = xg1[1024 + j], xo1 = xg1[2048 + j], xq1 = xg1[3072 + j];

        ull a0if = 0ull, a0og = 0ull, a1if = 0ull, a1og = 0ull;

        // stage chunk 0 (64 k x 64 b x 4B = 16 KB, contiguous)
#pragma unroll
        for (int i2 = 0; i2 < 4; ++i2) {
            int off = (tid + i2 * 256) * 4;
            cp16(&hb[off], &hin[off]);
        }
        asm volatile("cp.async.commit_group;" ::: "memory");

        for (int kc = 0; kc < 16; ++kc) {
            int buf = kc & 1;
            if (kc + 1 < 16) {
                const float* src = &hin[(kc + 1) * 4096];
                float* dst = &hb[(buf ^ 1) * 4096];
#pragma unroll
                for (int i2 = 0; i2 < 4; ++i2) {
                    int off = (tid + i2 * 256) * 4;
                    cp16(&dst[off], &src[off]);
                }
                asm volatile("cp.async.commit_group;" ::: "memory");
                asm volatile("cp.async.wait_group 1;" ::: "memory");
            } else {
                asm volatile("cp.async.wait_group 0;" ::: "memory");
            }
            __syncthreads();
            const float* wrow = &ws[(kc * 64) * 32 + jj * 4];
            const float* hrow = &hb[buf * 4096 + b0];
#pragma unroll
            for (int k = 0; k < 64; ++k) {
                ulonglong2 wp = *(const ulonglong2*)(wrow + k * 32);
                float2 hp = *(const float2*)(hrow + k * 64);
                ull h0 = dup2(hp.x), h1 = dup2(hp.y);
                a0if = ffma2(h0, wp.x, a0if);
                a0og = ffma2(h0, wp.y, a0og);
                a1if = ffma2(h1, wp.x, a1if);
                a1og = ffma2(h1, wp.y, a1og);
            }
            __syncthreads();
        }

        // gate math + state update (c in registers; this thread owns (b,j))
        {
            float gi = lo2(a0if) + xi0, gf = hi2(a0if) + xf0;
            float go = lo2(a0og) + xo0, gg = hi2(a0og) + xq0;
            float ii = 1.f / (1.f + expf(-gi));
            float ff = 1.f / (1.f + expf(-gf));
            float oo = 1.f / (1.f + expf(-go));
            c0 = ff * c0 + ii * tanhf(gg);
            hn0 = oo * tanhf(c0);

            gi = lo2(a1if) + xi1; gf = hi2(a1if) + xf1;
            go = lo2(a1og) + xo1; gg = hi2(a1og) + xq1;
            ii = 1.f / (1.f + expf(-gi));
            ff = 1.f / (1.f + expf(-gf));
            oo = 1.f / (1.f + expf(-go));
            c1 = ff * c1 + ii * tanhf(gg);
            hn1 = oo * tanhf(c1);
        }
        *(float2*)&hout[j * 64 + b0] = make_float2(hn0, hn1);
        out[((size_t)b0 * S_ + t) * H_ + j] = hn0;
        out[((size_t)b1 * S_ + t) * H_ + j] = hn1;

        grid_barrier();
    }

    // tail: (h, c) in flattening order (outputs, h, c), guarded by out_size
    long long base = (long long)B_ * S_ * H_;
    long long i0 = (long long)b0 * H_ + j;
    long long i1 = (long long)b1 * H_ + j;
    if (base + i0 < out_size) out[base + i0] = hn0;
    if (base + i1 < out_size) out[base + i1] = hn1;
    if (base + (long long)B_ * H_ + i0 < out_size) out[base + (long long)B_ * H_ + i0] = c0;
    if (base + (long long)B_ * H_ + i1 < out_size) out[base + (long long)B_ * H_ + i1] = c1;
}

// ---------------------------------------------------------------------------
extern "C" void kernel_launch(void* const* d_in, const int* in_sizes, int n_in,
                              void* d_out, int out_size) {
    const float* x    = (const float*)d_in[0];   // [64, 512, 1024]
    const float* W    = (const float*)d_in[1];   // [4096, 2048]
    const float* bias = (const float*)d_in[2];   // [4096]
    float* out = (float*)d_out;

    const int SMEM_BYTES = (32768 + 8192) * 4;   // 160 KB
    cudaFuncSetAttribute(lstm_persistent,
                         cudaFuncAttributeMaxDynamicSharedMemorySize, SMEM_BYTES);

    transpose_W<<<dim3(64, 128), dim3(32, 8)>>>(W);
    pack_Wh<<<(H_ * G_) / 256, 256>>>();
    zero_state<<<(B_ * H_ + 255) / 256, 256>>>();
    sgemm_xw<<<dim3(G_ / 128, BS_ / 128), 256>>>(x, bias);

    lstm_persistent<<<NBLK, 256, SMEM_BYTES>>>(out, (long long)out_size);
}

// round 13
// speedup vs baseline: 1.9338x; 1.2094x over previous
#include <cuda_runtime.h>
#include <cuda_bf16.h>
#include <math.h>

// Problem constants
#define B_   64
#define S_   512
#define D_   1024
#define H_   1024
#define G_   4096      // 4*H
#define DPH  2048      // D + H
#define BS_  (B_ * S_) // 32768 rows of x
#define NBLK 128       // persistent grid (<=148 SMs, 1 block/SM)

typedef unsigned long long ull;

// One canonical dynamic-shared symbol for the whole TU.
extern __shared__ __align__(1024) char dynsm[];

// ---------------------------------------------------------------------------
// Packed fp32x2 helpers (Blackwell FFMA2 — full-rate fp32 path)
// ---------------------------------------------------------------------------
__device__ __forceinline__ ull ffma2(ull a, ull b, ull c) {
    ull d;
    asm("fma.rn.f32x2 %0, %1, %2, %3;" : "=l"(d) : "l"(a), "l"(b), "l"(c));
    return d;
}
__device__ __forceinline__ ull dup2(float x) {
    ull d; unsigned xi = __float_as_uint(x);
    asm("mov.b64 %0, {%1, %1};" : "=l"(d) : "r"(xi));
    return d;
}
__device__ __forceinline__ float lo2(ull v) { return __uint_as_float((unsigned)v); }
__device__ __forceinline__ float hi2(ull v) { return __uint_as_float((unsigned)(v >> 32)); }

__device__ __forceinline__ void cp16(void* smem, const void* g) {
    unsigned s = (unsigned)__cvta_generic_to_shared(smem);
    asm volatile("cp.async.cg.shared.global [%0], [%1], 16;" :: "r"(s), "l"(g));
}
#define CP_COMMIT()  asm volatile("cp.async.commit_group;" ::: "memory")

// bf16 mma: D(16x8,f32) += A(16x16,bf16) * B(16x8,bf16)   [baseline PTX, sm_80+]
__device__ __forceinline__ void mma_bf16(float* d,
                                         unsigned a0, unsigned a1, unsigned a2, unsigned a3,
                                         unsigned b0, unsigned b1) {
    asm volatile(
        "mma.sync.aligned.m16n8k16.row.col.f32.bf16.bf16.f32 "
        "{%0,%1,%2,%3}, {%4,%5,%6,%7}, {%8,%9}, {%0,%1,%2,%3};"
        : "+f"(d[0]), "+f"(d[1]), "+f"(d[2]), "+f"(d[3])
        : "r"(a0), "r"(a1), "r"(a2), "r"(a3), "r"(b0), "r"(b1));
}

// ---------------------------------------------------------------------------
// Scratch (static device globals — no allocations allowed)
// ---------------------------------------------------------------------------
__device__ float g_Whp[(size_t)H_ * G_];          // packed Wh: [k][j][gate] (16 MB)
__device__ float g_Xg[(size_t)BS_ * G_];          // x @ Wx^T + b (512 MB)
__device__ __align__(16) float g_h[2][H_][B_];    // h state, k-major
__device__ __nv_bfloat16 g_xhi[(size_t)BS_ * D_]; // 64 MB
__device__ __nv_bfloat16 g_xlo[(size_t)BS_ * D_]; // 64 MB
__device__ __nv_bfloat16 g_whi[(size_t)G_ * D_];  //  8 MB (W[:, :1024])
__device__ __nv_bfloat16 g_wlo[(size_t)G_ * D_];  //  8 MB
__device__ volatile unsigned g_bar_gen;
__device__ unsigned g_bar_count;

// ---------------------------------------------------------------------------
// Convert x -> bf16 hi/lo split
// ---------------------------------------------------------------------------
__global__ void conv_x(const float* __restrict__ x) {
    size_t i = (size_t)blockIdx.x * 256 + threadIdx.x;   // one float4 each
    float4 v = *(const float4*)(x + i * 4);
    float f[4] = {v.x, v.y, v.z, v.w};
    unsigned short hi[4], lo[4];
#pragma unroll
    for (int c = 0; c < 4; c++) {
        __nv_bfloat16 h = __float2bfloat16_rn(f[c]);
        __nv_bfloat16 l = __float2bfloat16_rn(f[c] - __bfloat162float(h));
        hi[c] = *(unsigned short*)&h;
        lo[c] = *(unsigned short*)&l;
    }
    *(ushort4*)(g_xhi + i * 4) = make_ushort4(hi[0], hi[1], hi[2], hi[3]);
    *(ushort4*)(g_xlo + i * 4) = make_ushort4(lo[0], lo[1], lo[2], lo[3]);
}

// ---------------------------------------------------------------------------
// Convert W[:, 0:1024] -> bf16 hi/lo split  (W row stride = 2048)
// ---------------------------------------------------------------------------
__global__ void conv_w(const float* __restrict__ W) {
    size_t i = (size_t)blockIdx.x * 256 + threadIdx.x;   // one float4 each
    size_t n = (i * 4) >> 10;
    size_t k = (i * 4) & 1023;
    float4 v = *(const float4*)(W + n * DPH + k);
    float f[4] = {v.x, v.y, v.z, v.w};
    unsigned short hi[4], lo[4];
#pragma unroll
    for (int c = 0; c < 4; c++) {
        __nv_bfloat16 h = __float2bfloat16_rn(f[c]);
        __nv_bfloat16 l = __float2bfloat16_rn(f[c] - __bfloat162float(h));
        hi[c] = *(unsigned short*)&h;
        lo[c] = *(unsigned short*)&l;
    }
    *(ushort4*)(g_whi + i * 4) = make_ushort4(hi[0], hi[1], hi[2], hi[3]);
    *(ushort4*)(g_wlo + i * 4) = make_ushort4(lo[0], lo[1], lo[2], lo[3]);
}

// ---------------------------------------------------------------------------
// Pack recurrent weights straight from W:
// Whp[(k*1024 + j)*4 + g] = W[g*1024 + j][1024 + k]
// ---------------------------------------------------------------------------
__global__ void pack_Wh(const float* __restrict__ W) {
    int idx = blockIdx.x * 256 + threadIdx.x;
    int g = idx & 3;
    int j = (idx >> 2) & 1023;
    int k = idx >> 12;
    g_Whp[idx] = W[(size_t)(g * 1024 + j) * DPH + 1024 + k];
}

// ---------------------------------------------------------------------------
// Zero h buffers, reset grid barrier
// ---------------------------------------------------------------------------
__global__ void zero_state() {
    int i = blockIdx.x * 256 + threadIdx.x;
    if (i < B_ * H_) {
        int j = i >> 6, b = i & 63;
        g_h[0][j][b] = 0.f;
        g_h[1][j][b] = 0.f;
    }
    if (i == 0) { g_bar_count = 0; g_bar_gen = 0; }
}

// ---------------------------------------------------------------------------
// Input GEMM via warp-level bf16 mma (HMMA) with hi/lo split:
//   Xg[m][n] = sum_k x[m][k]*W[n][k] + bias[n],  M=32768, N=4096, K=1024
// CTA 128x128, 8 warps (2m x 4n), warp tile 64x32, m16n8k16.
// K-chunks of 32; smem arrays Ahi/Alo/Bhi/Blo [128 rows][32 bf16], row
// stride 80 B (conflict-free: bank = (20r + t) & 31 distinct per quad).
// Three mma passes: hi*hi + hi*lo + lo*hi, fp32 accumulators.
// ---------------------------------------------------------------------------
#define GNC     32                  // k-chunks (1024/32)
#define ROWB    80                  // padded row stride in bytes
#define ARR_B   (128 * ROWB)        // 10240 B per array
#define SLOT_B  (4 * ARR_B)         // 40960 B per ring slot

// smem element address: array base (char*), row r, bf16-column c
#define SMEL(base, r, c) (*(const unsigned*)((const char*)(base) + (r) * ROWB + (c) * 2))

__global__ __launch_bounds__(256) void gemm_mma(const float* __restrict__ bias) {
    char* sm = dynsm;
    const int tid  = threadIdx.x;
    const int warp = tid >> 5, lane = tid & 31;
    const int wm = warp >> 2, wn = warp & 3;         // 2 x 4 warp grid
    const int gq = lane >> 2, tq = lane & 3;         // quad row / quad thread
    const int bn = blockIdx.x * 128;
    const int bm = blockIdx.y * 128;

    float acc[4][4][4];                               // [mt][nt][frag]
#pragma unroll
    for (int a = 0; a < 4; a++)
#pragma unroll
        for (int b = 0; b < 4; b++)
#pragma unroll
            for (int c = 0; c < 4; c++) acc[a][b][c] = 0.f;

    // stage chunk kc into slot s (Ahi|Alo|Bhi|Blo, 128 rows x 32 bf16 each)
    auto stage = [&](int kc, int s) {
        int k0 = kc * 32;
        char* slot = sm + s * SLOT_B;
#pragma unroll
        for (int i = 0; i < 2; ++i) {
            int e = tid + i * 256;          // 0..511
            int r = e >> 2, seg = e & 3;    // row, 16B segment
            char* dst = slot + r * ROWB + seg * 16;
            const __nv_bfloat16* sa = g_xhi + (size_t)(bm + r) * D_ + k0 + seg * 8;
            cp16(dst, sa);
            cp16(dst + ARR_B, g_xlo + (size_t)(bm + r) * D_ + k0 + seg * 8);
            cp16(dst + 2 * ARR_B, g_whi + (size_t)(bn + r) * D_ + k0 + seg * 8);
            cp16(dst + 3 * ARR_B, g_wlo + (size_t)(bn + r) * D_ + k0 + seg * 8);
        }
    };

    stage(0, 0); CP_COMMIT();

    for (int kc = 0; kc < GNC; ++kc) {
        int s = kc & 1;
        if (kc + 1 < GNC) {
            stage(kc + 1, s ^ 1); CP_COMMIT();
            asm volatile("cp.async.wait_group 1;" ::: "memory");
        } else {
            asm volatile("cp.async.wait_group 0;" ::: "memory");
        }
        __syncthreads();

        const char* Ahi = sm + s * SLOT_B;
        const char* Alo = Ahi + ARR_B;
        const char* Bhi = Ahi + 2 * ARR_B;
        const char* Blo = Ahi + 3 * ARR_B;

#pragma unroll
        for (int kk = 0; kk < 32; kk += 16) {
            // B fragments for 4 n-tiles (hi and lo)
            unsigned bh[4][2], bl[4][2];
#pragma unroll
            for (int nt = 0; nt < 4; ++nt) {
                int nr = wn * 32 + nt * 8 + gq;
                bh[nt][0] = SMEL(Bhi, nr, kk + 2 * tq);
                bh[nt][1] = SMEL(Bhi, nr, kk + 2 * tq + 8);
                bl[nt][0] = SMEL(Blo, nr, kk + 2 * tq);
                bl[nt][1] = SMEL(Blo, nr, kk + 2 * tq + 8);
            }
#pragma unroll
            for (int mt = 0; mt < 4; ++mt) {
                int mr = wm * 64 + mt * 16 + gq;
                unsigned a0 = SMEL(Ahi, mr,     kk + 2 * tq);
                unsigned a1 = SMEL(Ahi, mr + 8, kk + 2 * tq);
                unsigned a2 = SMEL(Ahi, mr,     kk + 2 * tq + 8);
                unsigned a3 = SMEL(Ahi, mr + 8, kk + 2 * tq + 8);
#pragma unroll
                for (int nt = 0; nt < 4; ++nt) {
                    mma_bf16(acc[mt][nt], a0, a1, a2, a3, bh[nt][0], bh[nt][1]);
                    mma_bf16(acc[mt][nt], a0, a1, a2, a3, bl[nt][0], bl[nt][1]);
                }
                a0 = SMEL(Alo, mr,     kk + 2 * tq);
                a1 = SMEL(Alo, mr + 8, kk + 2 * tq);
                a2 = SMEL(Alo, mr,     kk + 2 * tq + 8);
                a3 = SMEL(Alo, mr + 8, kk + 2 * tq + 8);
#pragma unroll
                for (int nt = 0; nt < 4; ++nt)
                    mma_bf16(acc[mt][nt], a0, a1, a2, a3, bh[nt][0], bh[nt][1]);
            }
        }
        __syncthreads();
    }

    // epilogue: D frag c0,c1 -> row g, cols 2t,2t+1 ; c2,c3 -> row g+8
#pragma unroll
    for (int mt = 0; mt < 4; ++mt) {
        size_t r0 = (size_t)(bm + wm * 64 + mt * 16 + gq);
        size_t r1 = r0 + 8;
#pragma unroll
        for (int nt = 0; nt < 4; ++nt) {
            int n = bn + wn * 32 + nt * 8 + 2 * tq;
            float2 bv = *(const float2*)&bias[n];
            float2 v0 = make_float2(acc[mt][nt][0] + bv.x, acc[mt][nt][1] + bv.y);
            float2 v1 = make_float2(acc[mt][nt][2] + bv.x, acc[mt][nt][3] + bv.y);
            *(float2*)&g_Xg[r0 * G_ + n] = v0;
            *(float2*)&g_Xg[r1 * G_ + n] = v1;
        }
    }
}

// ---------------------------------------------------------------------------
// Device-wide barrier (all NBLK blocks resident by construction).
// ---------------------------------------------------------------------------
__device__ __forceinline__ void grid_barrier() {
    __syncthreads();
    if (threadIdx.x == 0) {
        __threadfence();
        unsigned gen = g_bar_gen;
        if (atomicAdd(&g_bar_count, 1u) == NBLK - 1) {
            g_bar_count = 0;
            __threadfence();
            g_bar_gen = gen + 1;
        } else {
            while (g_bar_gen == gen) { }
        }
        __threadfence();
    }
    __syncthreads();
}

// ---------------------------------------------------------------------------
// Persistent LSTM: all 512 timesteps in one kernel.
// 128 blocks; block owns 8 j-columns (all 4 gates) x all 64 batches.
// Weight slice (128 KB) resident in smem; h staged per 64-k chunk via
// ring-3 cp.async buffers, ONE __syncthreads per chunk. c in registers.
// Dynamic smem: ws 128 KB + hb 3x16 KB = 176 KB.
// ---------------------------------------------------------------------------
__global__ __launch_bounds__(256) void lstm_persistent(float* __restrict__ out,
                                                       long long out_size) {
    float* smf = (float*)dynsm;
    float* ws = smf;              // [1024][32]
    float* hb = smf + 32768;      // [3][64][64]

    const int tid = threadIdx.x;
    const int jj = tid & 7, bp = tid >> 3;
    const int b0 = bp * 2, b1 = b0 + 1;
    const int j0 = blockIdx.x * 8;
    const int j  = j0 + jj;

    // preload this block's weight slice once (1024 rows x 128 B)
    for (int i = tid; i < 8192; i += 256) {
        int r = i >> 3, seg = (i & 7) * 4;
        cp16(&ws[r * 32 + seg], &g_Whp[(size_t)r * G_ + j0 * 4 + seg]);
    }
    CP_COMMIT();
    asm volatile("cp.async.wait_group 0;" ::: "memory");
    __syncthreads();

    float c0 = 0.f, c1 = 0.f, hn0 = 0.f, hn1 = 0.f;

    for (int t = 0; t < S_; ++t) {
        const float* __restrict__ hin  = &g_h[t & 1][0][0];
        float* __restrict__       hout = &g_h[(t + 1) & 1][0][0];

        // prefetch x-gate biases for this step
        const float* xg0 = &g_Xg[((size_t)b0 * S_ + t) * G_];
        const float* xg1 = &g_Xg[((size_t)b1 * S_ + t) * G_];
        float xi0 = xg0[j], xf0 = xg0[1024 + j], xo0 = xg0[2048 + j], xq0 = xg0[3072 + j];
        float xi1 = xg1[j], xf1 = xg1[1024 + j], xo1 = xg1[2048 + j], xq1 = xg1[3072 + j];

        ull a0if = 0ull, a0og = 0ull, a1if = 0ull, a1og = 0ull;

        // stage chunk cc (64 k x 64 b = 16 KB) into ring slot s
        auto stage = [&](int cc, int s) {
            const float* src = &hin[cc * 4096];
            float* dst = &hb[s * 4096];
#pragma unroll
            for (int i2 = 0; i2 < 4; ++i2) {
                int off = (tid + i2 * 256) * 4;
                cp16(&dst[off], &src[off]);
            }
        };

        stage(0, 0); CP_COMMIT();
        stage(1, 1); CP_COMMIT();

        for (int kc = 0; kc < 16; ++kc) {
            int s = kc % 3;
            if (kc < 15)
                asm volatile("cp.async.wait_group 1;" ::: "memory");
            else
                asm volatile("cp.async.wait_group 0;" ::: "memory");
            __syncthreads();

            const float* wrow = &ws[(kc * 64) * 32 + jj * 4];
            const float* hrow = &hb[s * 4096 + b0];
#pragma unroll
            for (int k = 0; k < 64; ++k) {
                ulonglong2 wp = *(const ulonglong2*)(wrow + k * 32);
                float2 hp = *(const float2*)(hrow + k * 64);
                ull h0 = dup2(hp.x), h1 = dup2(hp.y);
                a0if = ffma2(h0, wp.x, a0if);
                a0og = ffma2(h0, wp.y, a0og);
                a1if = ffma2(h1, wp.x, a1if);
                a1og = ffma2(h1, wp.y, a1og);
            }

            if (kc <= 13) {             // stage kc+2 into slot (kc+2)%3
                stage(kc + 2, (kc + 2) % 3);
                CP_COMMIT();
            }
        }

        // gate math + state update (c in registers; thread owns (b,j))
        {
            float gi = lo2(a0if) + xi0, gf = hi2(a0if) + xf0;
            float go = lo2(a0og) + xo0, gg = hi2(a0og) + xq0;
            float ii = 1.f / (1.f + expf(-gi));
            float ff = 1.f / (1.f + expf(-gf));
            float oo = 1.f / (1.f + expf(-go));
            c0 = ff * c0 + ii * tanhf(gg);
            hn0 = oo * tanhf(c0);

            gi = lo2(a1if) + xi1; gf = hi2(a1if) + xf1;
            go = lo2(a1og) + xo1; gg = hi2(a1og) + xq1;
            ii = 1.f / (1.f + expf(-gi));
            ff = 1.f / (1.f + expf(-gf));
            oo = 1.f / (1.f + expf(-go));
            c1 = ff * c1 + ii * tanhf(gg);
            hn1 = oo * tanhf(c1);
        }
        *(float2*)&hout[j * 64 + b0] = make_float2(hn0, hn1);
        out[((size_t)b0 * S_ + t) * H_ + j] = hn0;
        out[((size_t)b1 * S_ + t) * H_ + j] = hn1;

        grid_barrier();
    }

    // tail: (h, c) in flattening order (outputs, h, c), guarded by out_size
    long long base = (long long)B_ * S_ * H_;
    long long i0 = (long long)b0 * H_ + j;
    long long i1 = (long long)b1 * H_ + j;
    if (base + i0 < out_size) out[base + i0] = hn0;
    if (base + i1 < out_size) out[base + i1] = hn1;
    if (base + (long long)B_ * H_ + i0 < out_size) out[base + (long long)B_ * H_ + i0] = c0;
    if (base + (long long)B_ * H_ + i1 < out_size) out[base + (long long)B_ * H_ + i1] = c1;
}

// ---------------------------------------------------------------------------
extern "C" void kernel_launch(void* const* d_in, const int* in_sizes, int n_in,
                              void* d_out, int out_size) {
    const float* x    = (const float*)d_in[0];   // [64, 512, 1024]
    const float* W    = (const float*)d_in[1];   // [4096, 2048]
    const float* bias = (const float*)d_in[2];   // [4096]
    float* out = (float*)d_out;

    const int GEMM_SMEM = 2 * SLOT_B;                      // 80 KB
    const int LSTM_SMEM = (32768 + 3 * 4096) * 4;          // 176 KB
    cudaFuncSetAttribute(gemm_mma,
                         cudaFuncAttributeMaxDynamicSharedMemorySize, GEMM_SMEM);
    cudaFuncSetAttribute(lstm_persistent,
                         cudaFuncAttributeMaxDynamicSharedMemorySize, LSTM_SMEM);

    conv_x<<<(BS_ * D_ / 4) / 256, 256>>>(x);
    conv_w<<<((size_t)G_ * D_ / 4) / 256, 256>>>(W);
    pack_Wh<<<(H_ * G_) / 256, 256>>>(W);
    zero_state<<<(B_ * H_ + 255) / 256, 256>>>();

    gemm_mma<<<dim3(G_ / 128, BS_ / 128), 256, GEMM_SMEM>>>(bias);

    lstm_persistent<<<NBLK, 256, LSTM_SMEM>>>(out, (long long)out_size);
}

// round 16
// speedup vs baseline: 3.5753x; 1.8489x over previous
#include <cuda_runtime.h>
#include <cuda_bf16.h>
#include <math.h>

// Problem constants
#define B_   64
#define S_   512
#define D_   1024
#define H_   1024
#define G_   4096      // 4*H
#define DPH  2048      // D + H
#define BS_  (B_ * S_) // 32768 rows of x
#define NBLK 128       // persistent grid (<=148 SMs, 1 block/SM)

typedef unsigned long long ull;

// One canonical dynamic-shared symbol for the whole TU.
extern __shared__ __align__(1024) char dynsm[];

// ---------------------------------------------------------------------------
__device__ __forceinline__ void cp16(void* smem, const void* g) {
    unsigned s = (unsigned)__cvta_generic_to_shared(smem);
    asm volatile("cp.async.cg.shared.global [%0], [%1], 16;" :: "r"(s), "l"(g));
}
#define CP_COMMIT()  asm volatile("cp.async.commit_group;" ::: "memory")

// bf16 mma: D(16x8,f32) += A(16x16,bf16) * B(16x8,bf16)   [baseline PTX, sm_80+]
__device__ __forceinline__ void mma_bf16(float* d,
                                         unsigned a0, unsigned a1, unsigned a2, unsigned a3,
                                         unsigned b0, unsigned b1) {
    asm volatile(
        "mma.sync.aligned.m16n8k16.row.col.f32.bf16.bf16.f32 "
        "{%0,%1,%2,%3}, {%4,%5,%6,%7}, {%8,%9}, {%0,%1,%2,%3};"
        : "+f"(d[0]), "+f"(d[1]), "+f"(d[2]), "+f"(d[3])
        : "r"(a0), "r"(a1), "r"(a2), "r"(a3), "r"(b0), "r"(b1));
}

// ---------------------------------------------------------------------------
// Scratch (static device globals — no allocations allowed)
// ---------------------------------------------------------------------------
__device__ float g_Xg[(size_t)BS_ * G_];            // x @ Wx^T + b (512 MB)
__device__ __nv_bfloat16 g_xhi[(size_t)BS_ * D_];   // 64 MB
__device__ __nv_bfloat16 g_xlo[(size_t)BS_ * D_];   // 64 MB
__device__ __nv_bfloat16 g_whi[(size_t)G_ * D_];    //  8 MB (W[:, :1024] for GEMM)
__device__ __nv_bfloat16 g_wlo[(size_t)G_ * D_];    //  8 MB
__device__ __nv_bfloat16 g_whh_hi[(size_t)G_ * H_]; //  8 MB  [c=j*4+g][k]
__device__ __nv_bfloat16 g_whh_lo[(size_t)G_ * H_]; //  8 MB
__device__ __nv_bfloat16 g_hhi[2][B_ * H_];         // h hi, [b][k], double-buffered
__device__ __nv_bfloat16 g_hlo[2][B_ * H_];         // h lo
__device__ volatile unsigned g_bar_gen;
__device__ unsigned g_bar_count;

// ---------------------------------------------------------------------------
// Convert x -> bf16 hi/lo split
// ---------------------------------------------------------------------------
__global__ void conv_x(const float* __restrict__ x) {
    size_t i = (size_t)blockIdx.x * 256 + threadIdx.x;   // one float4 each
    float4 v = *(const float4*)(x + i * 4);
    float f[4] = {v.x, v.y, v.z, v.w};
    unsigned short hi[4], lo[4];
#pragma unroll
    for (int c = 0; c < 4; c++) {
        __nv_bfloat16 h = __float2bfloat16_rn(f[c]);
        __nv_bfloat16 l = __float2bfloat16_rn(f[c] - __bfloat162float(h));
        hi[c] = *(unsigned short*)&h;
        lo[c] = *(unsigned short*)&l;
    }
    *(ushort4*)(g_xhi + i * 4) = make_ushort4(hi[0], hi[1], hi[2], hi[3]);
    *(ushort4*)(g_xlo + i * 4) = make_ushort4(lo[0], lo[1], lo[2], lo[3]);
}

// ---------------------------------------------------------------------------
// Convert W[:, 0:1024] -> bf16 hi/lo split  (W row stride = 2048)
// ---------------------------------------------------------------------------
__global__ void conv_w(const float* __restrict__ W) {
    size_t i = (size_t)blockIdx.x * 256 + threadIdx.x;   // one float4 each
    size_t n = (i * 4) >> 10;
    size_t k = (i * 4) & 1023;
    float4 v = *(const float4*)(W + n * DPH + k);
    float f[4] = {v.x, v.y, v.z, v.w};
    unsigned short hi[4], lo[4];
#pragma unroll
    for (int c = 0; c < 4; c++) {
        __nv_bfloat16 h = __float2bfloat16_rn(f[c]);
        __nv_bfloat16 l = __float2bfloat16_rn(f[c] - __bfloat162float(h));
        hi[c] = *(unsigned short*)&h;
        lo[c] = *(unsigned short*)&l;
    }
    *(ushort4*)(g_whi + i * 4) = make_ushort4(hi[0], hi[1], hi[2], hi[3]);
    *(ushort4*)(g_wlo + i * 4) = make_ushort4(lo[0], lo[1], lo[2], lo[3]);
}

// ---------------------------------------------------------------------------
// Pack recurrent weights as bf16 hi/lo, c-major: whh[c=j*4+g][k] =
//   split(W[g*1024 + j][1024 + k])
// ---------------------------------------------------------------------------
__global__ void pack_whh(const float* __restrict__ W) {
    size_t idx = (size_t)blockIdx.x * 256 + threadIdx.x;  // 0..4M-1
    int k = (int)(idx & 1023);
    int c = (int)(idx >> 10);
    int j = c >> 2, g = c & 3;
    float v = W[(size_t)(g * 1024 + j) * DPH + 1024 + k];
    __nv_bfloat16 h = __float2bfloat16_rn(v);
    __nv_bfloat16 l = __float2bfloat16_rn(v - __bfloat162float(h));
    g_whh_hi[idx] = h;
    g_whh_lo[idx] = l;
}

// ---------------------------------------------------------------------------
// Zero h buffers (buffer 0), reset grid barrier
// ---------------------------------------------------------------------------
__global__ void zero_state() {
    int i = blockIdx.x * 256 + threadIdx.x;
    if (i < B_ * H_) {
        g_hhi[0][i] = __float2bfloat16(0.f);
        g_hlo[0][i] = __float2bfloat16(0.f);
    }
    if (i == 0) { g_bar_count = 0; g_bar_gen = 0; }
}

// ---------------------------------------------------------------------------
// Input GEMM via warp-level bf16 mma (HMMA) with hi/lo split  (unchanged,
// validated in R13):  Xg[m][n] = sum_k x[m][k]*W[n][k] + bias[n]
// ---------------------------------------------------------------------------
#define GNC     32                  // k-chunks (1024/32)
#define ROWB    80                  // padded row stride in bytes
#define ARR_B   (128 * ROWB)        // 10240 B per array
#define SLOT_B  (4 * ARR_B)         // 40960 B per ring slot

#define SMEL(base, r, c) (*(const unsigned*)((const char*)(base) + (r) * ROWB + (c) * 2))

__global__ __launch_bounds__(256) void gemm_mma(const float* __restrict__ bias) {
    char* sm = dynsm;
    const int tid  = threadIdx.x;
    const int warp = tid >> 5, lane = tid & 31;
    const int wm = warp >> 2, wn = warp & 3;
    const int gq = lane >> 2, tq = lane & 3;
    const int bn = blockIdx.x * 128;
    const int bm = blockIdx.y * 128;

    float acc[4][4][4];
#pragma unroll
    for (int a = 0; a < 4; a++)
#pragma unroll
        for (int b = 0; b < 4; b++)
#pragma unroll
            for (int c = 0; c < 4; c++) acc[a][b][c] = 0.f;

    auto stage = [&](int kc, int s) {
        int k0 = kc * 32;
        char* slot = sm + s * SLOT_B;
#pragma unroll
        for (int i = 0; i < 2; ++i) {
            int e = tid + i * 256;
            int r = e >> 2, seg = e & 3;
            char* dst = slot + r * ROWB + seg * 16;
            cp16(dst, g_xhi + (size_t)(bm + r) * D_ + k0 + seg * 8);
            cp16(dst + ARR_B, g_xlo + (size_t)(bm + r) * D_ + k0 + seg * 8);
            cp16(dst + 2 * ARR_B, g_whi + (size_t)(bn + r) * D_ + k0 + seg * 8);
            cp16(dst + 3 * ARR_B, g_wlo + (size_t)(bn + r) * D_ + k0 + seg * 8);
        }
    };

    stage(0, 0); CP_COMMIT();

    for (int kc = 0; kc < GNC; ++kc) {
        int s = kc & 1;
        if (kc + 1 < GNC) {
            stage(kc + 1, s ^ 1); CP_COMMIT();
            asm volatile("cp.async.wait_group 1;" ::: "memory");
        } else {
            asm volatile("cp.async.wait_group 0;" ::: "memory");
        }
        __syncthreads();

        const char* Ahi = sm + s * SLOT_B;
        const char* Alo = Ahi + ARR_B;
        const char* Bhi = Ahi + 2 * ARR_B;
        const char* Blo = Ahi + 3 * ARR_B;

#pragma unroll
        for (int kk = 0; kk < 32; kk += 16) {
            unsigned bh[4][2], bl[4][2];
#pragma unroll
            for (int nt = 0; nt < 4; ++nt) {
                int nr = wn * 32 + nt * 8 + gq;
                bh[nt][0] = SMEL(Bhi, nr, kk + 2 * tq);
                bh[nt][1] = SMEL(Bhi, nr, kk + 2 * tq + 8);
                bl[nt][0] = SMEL(Blo, nr, kk + 2 * tq);
                bl[nt][1] = SMEL(Blo, nr, kk + 2 * tq + 8);
            }
#pragma unroll
            for (int mt = 0; mt < 4; ++mt) {
                int mr = wm * 64 + mt * 16 + gq;
                unsigned a0 = SMEL(Ahi, mr,     kk + 2 * tq);
                unsigned a1 = SMEL(Ahi, mr + 8, kk + 2 * tq);
                unsigned a2 = SMEL(Ahi, mr,     kk + 2 * tq + 8);
                unsigned a3 = SMEL(Ahi, mr + 8, kk + 2 * tq + 8);
#pragma unroll
                for (int nt = 0; nt < 4; ++nt) {
                    mma_bf16(acc[mt][nt], a0, a1, a2, a3, bh[nt][0], bh[nt][1]);
                    mma_bf16(acc[mt][nt], a0, a1, a2, a3, bl[nt][0], bl[nt][1]);
                }
                a0 = SMEL(Alo, mr,     kk + 2 * tq);
                a1 = SMEL(Alo, mr + 8, kk + 2 * tq);
                a2 = SMEL(Alo, mr,     kk + 2 * tq + 8);
                a3 = SMEL(Alo, mr + 8, kk + 2 * tq + 8);
#pragma unroll
                for (int nt = 0; nt < 4; ++nt)
                    mma_bf16(acc[mt][nt], a0, a1, a2, a3, bh[nt][0], bh[nt][1]);
            }
        }
        __syncthreads();
    }

#pragma unroll
    for (int mt = 0; mt < 4; ++mt) {
        size_t r0 = (size_t)(bm + wm * 64 + mt * 16 + gq);
        size_t r1 = r0 + 8;
#pragma unroll
        for (int nt = 0; nt < 4; ++nt) {
            int n = bn + wn * 32 + nt * 8 + 2 * tq;
            float2 bv = *(const float2*)&bias[n];
            float2 v0 = make_float2(acc[mt][nt][0] + bv.x, acc[mt][nt][1] + bv.y);
            float2 v1 = make_float2(acc[mt][nt][2] + bv.x, acc[mt][nt][3] + bv.y);
            *(float2*)&g_Xg[r0 * G_ + n] = v0;
            *(float2*)&g_Xg[r1 * G_ + n] = v1;
        }
    }
}

// ---------------------------------------------------------------------------
// Device-wide barrier (all NBLK blocks resident by construction).
// ---------------------------------------------------------------------------
__device__ __forceinline__ void grid_barrier() {
    __syncthreads();
    if (threadIdx.x == 0) {
        __threadfence();
        unsigned gen = g_bar_gen;
        if (atomicAdd(&g_bar_count, 1u) == NBLK - 1) {
            g_bar_count = 0;
            __threadfence();
            g_bar_gen = gen + 1;
        } else {
            while (g_bar_gen == gen) { }
        }
        __threadfence();
    }
    __syncthreads();
}

// ---------------------------------------------------------------------------
// Persistent LSTM with tensor-core recurrence.
// Per block (128 blocks): gates[64 b][32 c] = h[64 b][1024 k] @ WhhT, where
// c = jj*4 + gate, jj = local j (block owns j0..j0+7).
// Weights resident in smem as bf16 hi/lo [32][1024] (padded rows, 2064 B).
// h state global bf16 hi/lo [b][k]; staged per 128-k chunk, ring-2 cp.async.
// 3 mma passes (hi*hi + hi*lo + lo*hi). Gates -> smem -> pointwise phase
// identical to previous rounds (c state in registers).
//
// smem map (bytes):
//   [0, 66048)           Whh_hi  32 rows x 2064
//   [66048, 132096)      Whh_lo
//   [132096, 201728)     A ring: 2 slots x (Ahi 17408 + Alo 17408)
//   [201728, 210944)     gates buffer 64 x 36 floats
// ---------------------------------------------------------------------------
#define WHI_OFF   0
#define WLO_OFF   66048
#define WROWB     2064
#define ASLOT_OFF 132096
#define AARR_B    17408            // 64 rows x 272 B
#define AROWB     272
#define ASLOT_B   (2 * AARR_B)
#define GBUF_OFF  201728
#define LSTM_SMEM_B 210944

__global__ __launch_bounds__(256) void lstm_persistent(float* __restrict__ out,
                                                       long long out_size) {
    char* sm = dynsm;
    const int tid  = threadIdx.x;
    const int warp = tid >> 5, lane = tid & 31;
    const int wm = warp & 3;            // m-tile: batches wm*16..+15
    const int wn = warp >> 2;           // n-half: cols wn*16..+15
    const int gq = lane >> 2, tq = lane & 3;
    const int jj = tid & 7, bp = tid >> 3;
    const int b0 = bp * 2, b1 = b0 + 1;
    const int j0 = blockIdx.x * 8;
    const int j  = j0 + jj;

    // ---- preload recurrent weights (once): rows c=0..31 -> smem padded ----
    {
#pragma unroll
        for (int i = 0; i < 16; ++i) {
            int e = tid + i * 256;                 // 0..4095
            int r = e >> 7, seg = e & 127;         // row, 16B segment
            const __nv_bfloat16* shi = g_whh_hi + (size_t)(j0 * 4 + r) * H_ + seg * 8;
            const __nv_bfloat16* slo = g_whh_lo + (size_t)(j0 * 4 + r) * H_ + seg * 8;
            cp16(sm + WHI_OFF + r * WROWB + seg * 16, shi);
            cp16(sm + WLO_OFF + r * WROWB + seg * 16, slo);
        }
        CP_COMMIT();
        asm volatile("cp.async.wait_group 0;" ::: "memory");
        __syncthreads();
    }

    float c0 = 0.f, c1 = 0.f, hn0 = 0.f, hn1 = 0.f;
    float* gbuf = (float*)(sm + GBUF_OFF);

    for (int t = 0; t < S_; ++t) {
        const int inb  = t & 1;
        const int outb = (t + 1) & 1;
        const __nv_bfloat16* __restrict__ hhi = g_hhi[inb];
        const __nv_bfloat16* __restrict__ hlo = g_hlo[inb];

        // prefetch x-gate biases for this step
        const float* xg0 = &g_Xg[((size_t)b0 * S_ + t) * G_];
        const float* xg1 = &g_Xg[((size_t)b1 * S_ + t) * G_];
        float xi0 = xg0[j], xf0 = xg0[1024 + j], xo0 = xg0[2048 + j], xq0 = xg0[3072 + j];
        float xi1 = xg1[j], xf1 = xg1[1024 + j], xo1 = xg1[2048 + j], xq1 = xg1[3072 + j];

        float acc[2][4];
#pragma unroll
        for (int nt = 0; nt < 2; ++nt)
#pragma unroll
            for (int c = 0; c < 4; ++c) acc[nt][c] = 0.f;

        // stage h chunk kc (64 b x 128 k, hi+lo) into ring slot s
        auto stageH = [&](int kc, int s) {
            char* Ahi = sm + ASLOT_OFF + s * ASLOT_B;
            char* Alo = Ahi + AARR_B;
#pragma unroll
            for (int i = 0; i < 4; ++i) {
                int e = tid + i * 256;             // 0..1023
                int r = e >> 4, seg = e & 15;      // batch row, 16B segment
                size_t src = (size_t)r * H_ + kc * 128 + seg * 8;
                cp16(Ahi + r * AROWB + seg * 16, hhi + src);
                cp16(Alo + r * AROWB + seg * 16, hlo + src);
            }
        };

        stageH(0, 0); CP_COMMIT();

        for (int kc = 0; kc < 8; ++kc) {
            int s = kc & 1;
            if (kc + 1 < 8) {
                stageH(kc + 1, s ^ 1); CP_COMMIT();
                asm volatile("cp.async.wait_group 1;" ::: "memory");
            } else {
                asm volatile("cp.async.wait_group 0;" ::: "memory");
            }
            __syncthreads();

            const char* Ahi = sm + ASLOT_OFF + s * ASLOT_B;
            const char* Alo = Ahi + AARR_B;
            const char* Whi = sm + WHI_OFF;
            const char* Wlo = sm + WLO_OFF;
            const int kb = kc * 128;               // global k base for weights

#pragma unroll
            for (int kk = 0; kk < 128; kk += 16) {
                unsigned bh[2][2], bl[2][2];
#pragma unroll
                for (int nt = 0; nt < 2; ++nt) {
                    int nr = wn * 16 + nt * 8 + gq;
                    const char* wh = Whi + nr * WROWB + (kb + kk + 2 * tq) * 2;
                    const char* wl = Wlo + nr * WROWB + (kb + kk + 2 * tq) * 2;
                    bh[nt][0] = *(const unsigned*)wh;
                    bh[nt][1] = *(const unsigned*)(wh + 16);
                    bl[nt][0] = *(const unsigned*)wl;
                    bl[nt][1] = *(const unsigned*)(wl + 16);
                }
                int mr = wm * 16 + gq;
                const char* ah = Ahi + mr * AROWB + (kk + 2 * tq) * 2;
                const char* al = Alo + mr * AROWB + (kk + 2 * tq) * 2;
                unsigned a0 = *(const unsigned*)ah;
                unsigned a1 = *(const unsigned*)(ah + 8 * AROWB);
                unsigned a2 = *(const unsigned*)(ah + 16);
                unsigned a3 = *(const unsigned*)(ah + 8 * AROWB + 16);
                unsigned l0 = *(const unsigned*)al;
                unsigned l1 = *(const unsigned*)(al + 8 * AROWB);
                unsigned l2 = *(const unsigned*)(al + 16);
                unsigned l3 = *(const unsigned*)(al + 8 * AROWB + 16);
#pragma unroll
                for (int nt = 0; nt < 2; ++nt) {
                    mma_bf16(acc[nt], a0, a1, a2, a3, bh[nt][0], bh[nt][1]);
                    mma_bf16(acc[nt], a0, a1, a2, a3, bl[nt][0], bl[nt][1]);
                    mma_bf16(acc[nt], l0, l1, l2, l3, bh[nt][0], bh[nt][1]);
                }
            }
            __syncthreads();
        }

        // write gates to smem: rows=batch, cols=c (stride 36 floats)
        {
            int r0 = wm * 16 + gq, r1 = r0 + 8;
#pragma unroll
            for (int nt = 0; nt < 2; ++nt) {
                int c = wn * 16 + nt * 8 + 2 * tq;
                *(float2*)&gbuf[r0 * 36 + c] = make_float2(acc[nt][0], acc[nt][1]);
                *(float2*)&gbuf[r1 * 36 + c] = make_float2(acc[nt][2], acc[nt][3]);
            }
        }
        __syncthreads();

        // pointwise phase: thread owns (b0,j), (b1,j); c in registers
        {
            float4 gv0 = *(const float4*)&gbuf[b0 * 36 + jj * 4];
            float4 gv1 = *(const float4*)&gbuf[b1 * 36 + jj * 4];

            float gi = gv0.x + xi0, gf = gv0.y + xf0;
            float go = gv0.z + xo0, gg = gv0.w + xq0;
            float ii = 1.f / (1.f + expf(-gi));
            float ff = 1.f / (1.f + expf(-gf));
            float oo = 1.f / (1.f + expf(-go));
            c0 = ff * c0 + ii * tanhf(gg);
            hn0 = oo * tanhf(c0);

            gi = gv1.x + xi1; gf = gv1.y + xf1;
            go = gv1.z + xo1; gg = gv1.w + xq1;
            ii = 1.f / (1.f + expf(-gi));
            ff = 1.f / (1.f + expf(-gf));
            oo = 1.f / (1.f + expf(-go));
            c1 = ff * c1 + ii * tanhf(gg);
            hn1 = oo * tanhf(c1);
        }

        // write h (bf16 hi/lo for next step) + fp32 outputs
        {
            __nv_bfloat16 h0h = __float2bfloat16_rn(hn0);
            __nv_bfloat16 h0l = __float2bfloat16_rn(hn0 - __bfloat162float(h0h));
            __nv_bfloat16 h1h = __float2bfloat16_rn(hn1);
            __nv_bfloat16 h1l = __float2bfloat16_rn(hn1 - __bfloat162float(h1h));
            g_hhi[outb][b0 * H_ + j] = h0h;
            g_hlo[outb][b0 * H_ + j] = h0l;
            g_hhi[outb][b1 * H_ + j] = h1h;
            g_hlo[outb][b1 * H_ + j] = h1l;
            out[((size_t)b0 * S_ + t) * H_ + j] = hn0;
            out[((size_t)b1 * S_ + t) * H_ + j] = hn1;
        }

        grid_barrier();
    }

    // tail: (h, c) in flattening order (outputs, h, c), guarded by out_size
    long long base = (long long)B_ * S_ * H_;
    long long i0 = (long long)b0 * H_ + j;
    long long i1 = (long long)b1 * H_ + j;
    if (base + i0 < out_size) out[base + i0] = hn0;
    if (base + i1 < out_size) out[base + i1] = hn1;
    if (base + (long long)B_ * H_ + i0 < out_size) out[base + (long long)B_ * H_ + i0] = c0;
    if (base + (long long)B_ * H_ + i1 < out_size) out[base + (long long)B_ * H_ + i1] = c1;
}

// ---------------------------------------------------------------------------
extern "C" void kernel_launch(void* const* d_in, const int* in_sizes, int n_in,
                              void* d_out, int out_size) {
    const float* x    = (const float*)d_in[0];   // [64, 512, 1024]
    const float* W    = (const float*)d_in[1];   // [4096, 2048]
    const float* bias = (const float*)d_in[2];   // [4096]
    float* out = (float*)d_out;

    const int GEMM_SMEM = 2 * SLOT_B;            // 80 KB
    cudaFuncSetAttribute(gemm_mma,
                         cudaFuncAttributeMaxDynamicSharedMemorySize, GEMM_SMEM);
    cudaFuncSetAttribute(lstm_persistent,
                         cudaFuncAttributeMaxDynamicSharedMemorySize, LSTM_SMEM_B);

    conv_x<<<(BS_ * D_ / 4) / 256, 256>>>(x);
    conv_w<<<((size_t)G_ * D_ / 4) / 256, 256>>>(W);
    pack_whh<<<((size_t)G_ * H_) / 256, 256>>>(W);
    zero_state<<<(B_ * H_ + 255) / 256, 256>>>();

    gemm_mma<<<dim3(G_ / 128, BS_ / 128), 256, GEMM_SMEM>>>(bias);

    lstm_persistent<<<NBLK, 256, LSTM_SMEM_B>>>(out, (long long)out_size);
}